// round 12
// baseline (speedup 1.0000x reference)
#include <cuda_runtime.h>
#include <cstdint>

#define T_LEN 4096
#define CCH   256
#define BATCH 2

// ---------------- scratch (device globals; no allocation allowed) ----------
__device__ float g_xn [BATCH * CCH * T_LEN];          // normalized input [B,C,T]
__device__ float g_qkv[BATCH * 3 * CCH * T_LEN];      // qkv [B,3C,T]
__device__ float g_att[BATCH * CCH * T_LEN];          // attention out [B,C,T]

// ---------------- tf32 helpers --------------------------------------------
__device__ __forceinline__ uint32_t f2tf(float x) {
    uint32_t u;
    asm("cvt.rna.tf32.f32 %0, %1;" : "=r"(u) : "f"(x));
    return u;
}

__device__ __forceinline__ void mma_tf32(float* d, const uint32_t* a,
                                         uint32_t b0, uint32_t b1) {
    asm volatile(
        "mma.sync.aligned.m16n8k8.row.col.f32.tf32.tf32.f32 "
        "{%0,%1,%2,%3}, {%4,%5,%6,%7}, {%8,%9}, {%0,%1,%2,%3};"
        : "+f"(d[0]), "+f"(d[1]), "+f"(d[2]), "+f"(d[3])
        : "r"(a[0]), "r"(a[1]), "r"(a[2]), "r"(a[3]), "r"(b0), "r"(b1));
}

// ---------------- GroupNorm (32 groups of 8 channels, over C/G x T) --------
__global__ void gn_kernel(const float* __restrict__ x,
                          const float* __restrict__ w,
                          const float* __restrict__ bb) {
    int b = blockIdx.x >> 5, g = blockIdx.x & 31;
    const float* xp = x    + ((size_t)b * CCH + g * 8) * T_LEN;
    float*       op = g_xn + ((size_t)b * CCH + g * 8) * T_LEN;
    int tid = threadIdx.x;

    float s = 0.f, s2 = 0.f;
    for (int i = tid; i < 8 * T_LEN; i += 256) {
        float v = xp[i]; s += v; s2 += v * v;
    }
    __shared__ float rs[256], rq[256];
    rs[tid] = s; rq[tid] = s2; __syncthreads();
    for (int off = 128; off; off >>= 1) {
        if (tid < off) { rs[tid] += rs[tid + off]; rq[tid] += rq[tid + off]; }
        __syncthreads();
    }
    __shared__ float sm_mean, sm_rstd;
    if (tid == 0) {
        float mean = rs[0] * (1.f / (8.f * T_LEN));
        float var  = rq[0] * (1.f / (8.f * T_LEN)) - mean * mean;
        sm_mean = mean;
        sm_rstd = rsqrtf(var + 1e-5f);
    }
    __syncthreads();
    float mean = sm_mean, rstd = sm_rstd;
    for (int i = tid; i < 8 * T_LEN; i += 256) {
        int c = g * 8 + (i >> 12);
        op[i] = (xp[i] - mean) * rstd * w[c] + bb[c];
    }
}

// ---------------- GEMM on tensor cores (tf32), shared template -------------
// MODE 0 (QKV): C[768,4096] = qkv_w @ g_xn              (no epilogue)
// MODE 1 (proj): C[256,4096] = proj_w @ g_att + bias + resid
// Block: 256 thr = 8 warps; tile 128m x 64n; k staged 16 wide.
template <int MODE>
__global__ void gemm_mma_kernel(const float* __restrict__ Aw,
                                float* __restrict__ outg,
                                const float* __restrict__ bias,
                                const float* __restrict__ residg) {
    int z = blockIdx.z;
    const float* B = (MODE == 0) ? (g_xn  + (size_t)z * CCH * T_LEN)
                                 : (g_att + (size_t)z * CCH * T_LEN);
    float*       C = (MODE == 0) ? (g_qkv + (size_t)z * 3 * CCH * T_LEN)
                                 : (outg  + (size_t)z * CCH * T_LEN);
    int n0 = blockIdx.x * 64, m0 = blockIdx.y * 128;

    __shared__ float As[128 * 20];
    __shared__ float Bs[64 * 20];

    int tid = threadIdx.x, warp = tid >> 5, lane = tid & 31;
    int gq = lane >> 2, tg = lane & 3;

    float o[8][4] = {};

    for (int k0 = 0; k0 < 256; k0 += 16) {
        // stage A: 128x16, each thread one half-row (8 floats)
        {
            int mi = tid >> 1, j = (tid & 1) * 8;
            const float* src = &Aw[(size_t)(m0 + mi) * 256 + k0 + j];
            float4 v0 = *(const float4*)&src[0];
            float4 v1 = *(const float4*)&src[4];
            float* ap = &As[mi * 20 + j];
            ap[0] = __uint_as_float(f2tf(v0.x));
            ap[1] = __uint_as_float(f2tf(v0.y));
            ap[2] = __uint_as_float(f2tf(v0.z));
            ap[3] = __uint_as_float(f2tf(v0.w));
            ap[4] = __uint_as_float(f2tf(v1.x));
            ap[5] = __uint_as_float(f2tf(v1.y));
            ap[6] = __uint_as_float(f2tf(v1.z));
            ap[7] = __uint_as_float(f2tf(v1.w));
        }
        // stage B: 16k x 64n, transposed into Bs[n][k]
#pragma unroll
        for (int r = 0; r < 4; r++) {
            int idx = tid + r * 256;
            int k = idx >> 6, n = idx & 63;
            Bs[n * 20 + k] =
                __uint_as_float(f2tf(B[(size_t)(k0 + k) * T_LEN + n0 + n]));
        }
        __syncthreads();

#pragma unroll
        for (int kk = 0; kk < 2; kk++) {
            uint32_t a[4];
            const float* arow = &As[(warp * 16 + gq) * 20 + kk * 8 + tg];
            a[0] = __float_as_uint(arow[0]);
            a[1] = __float_as_uint(arow[8 * 20]);
            a[2] = __float_as_uint(arow[4]);
            a[3] = __float_as_uint(arow[8 * 20 + 4]);
#pragma unroll
            for (int nb = 0; nb < 8; nb++) {
                const float* bp = &Bs[(nb * 8 + gq) * 20 + kk * 8 + tg];
                mma_tf32(o[nb], a, __float_as_uint(bp[0]), __float_as_uint(bp[4]));
            }
        }
        __syncthreads();
    }

    int m = m0 + warp * 16 + gq;
#pragma unroll
    for (int nb = 0; nb < 8; nb++) {
        int col = n0 + nb * 8 + 2 * tg;
        float2 r0 = make_float2(o[nb][0], o[nb][1]);
        float2 r1 = make_float2(o[nb][2], o[nb][3]);
        if (MODE == 1) {
            const float* resid = residg + (size_t)z * CCH * T_LEN;
            float b0v = bias[m], b1v = bias[m + 8];
            float2 x0 = *(const float2*)&resid[(size_t)m * T_LEN + col];
            float2 x1 = *(const float2*)&resid[(size_t)(m + 8) * T_LEN + col];
            r0.x += b0v + x0.x; r0.y += b0v + x0.y;
            r1.x += b1v + x1.x; r1.y += b1v + x1.y;
        }
        *(float2*)&C[(size_t)m * T_LEN + col]       = r0;
        *(float2*)&C[(size_t)(m + 8) * T_LEN + col] = r1;
    }
}

// ---------------- flash attention: tf32 mma, 64-query CTAs ----------------
// Block: 64 queries (4 warps x 16 rows), KV tile 64, d=64. 3 CTAs/SM target.
// smem: Ks[64][68] ([s][d]), Vs[64][68] ([d][s]), Ps[64][68] (per-warp rows)
__global__ __launch_bounds__(128, 3) void flash_mma_kernel() {
    extern __shared__ float sm[];
    float* Ks = sm;                   // 64*68
    float* Vs = sm + 64 * 68;         // 64*68
    float* Ps = sm + 2 * 64 * 68;     // 64*68 (4 warps x 16 rows)

    int bh = blockIdx.y;
    int b = bh >> 2, hh = bh & 3;
    int t0 = blockIdx.x * 64;
    const float* qb = g_qkv + ((size_t)b * 768 + hh * 192) * T_LEN;
    const float* kb = qb + (size_t)64  * T_LEN;
    const float* vb = qb + (size_t)128 * T_LEN;

    int tid = threadIdx.x;
    int warp = tid >> 5, lane = tid & 31;
    int gq = lane >> 2, tg = lane & 3;     // groupID, threadInGroup
    int qrow0 = t0 + warp * 16 + gq;       // global q index of A-row "gq"

    // Q fragments (scale 1/8 folded in), tf32-rounded, register-resident
    uint32_t qa[8][4];
#pragma unroll
    for (int kk = 0; kk < 8; kk++) {
        int d0 = kk * 8 + tg;
        qa[kk][0] = f2tf(qb[(size_t)(d0)     * T_LEN + qrow0]     * 0.125f);
        qa[kk][1] = f2tf(qb[(size_t)(d0)     * T_LEN + qrow0 + 8] * 0.125f);
        qa[kk][2] = f2tf(qb[(size_t)(d0 + 4) * T_LEN + qrow0]     * 0.125f);
        qa[kk][3] = f2tf(qb[(size_t)(d0 + 4) * T_LEN + qrow0 + 8] * 0.125f);
    }

    float o[8][4] = {};
    float m0 = -1e30f, m1 = -1e30f, l0 = 0.f, l1 = 0.f;

    float* Pw = Ps + warp * 16 * 68;   // this warp's P slice

    for (int s0 = 0; s0 < T_LEN; s0 += 64) {
        // stage K [s][68] and V [d][68] (tf32-rounded once here)
        for (int idx = tid; idx < 4096; idx += 128) {
            int d = idx >> 6, s = idx & 63;
            float kv = kb[(size_t)d * T_LEN + s0 + s];
            float vv = vb[(size_t)d * T_LEN + s0 + s];
            Ks[s * 68 + d] = __uint_as_float(f2tf(kv));
            Vs[d * 68 + s] = __uint_as_float(f2tf(vv));
        }
        __syncthreads();

        // S = Q K^T : per warp 16x64, acc fragments s_[nb][4]
        float s_[8][4] = {};
#pragma unroll
        for (int kk = 0; kk < 8; kk++) {
#pragma unroll
            for (int nb = 0; nb < 8; nb++) {
                const float* kp = &Ks[(nb * 8 + gq) * 68 + kk * 8 + tg];
                uint32_t b0 = __float_as_uint(kp[0]);
                uint32_t b1 = __float_as_uint(kp[4]);
                mma_tf32(s_[nb], qa[kk], b0, b1);
            }
        }

        // online softmax: half 0 = rows gq (c0,c1), half 1 = rows gq+8 (c2,c3)
        float mx0 = -1e30f, mx1 = -1e30f;
#pragma unroll
        for (int nb = 0; nb < 8; nb++) {
            mx0 = fmaxf(mx0, fmaxf(s_[nb][0], s_[nb][1]));
            mx1 = fmaxf(mx1, fmaxf(s_[nb][2], s_[nb][3]));
        }
        mx0 = fmaxf(mx0, __shfl_xor_sync(0xffffffffu, mx0, 1));
        mx0 = fmaxf(mx0, __shfl_xor_sync(0xffffffffu, mx0, 2));
        mx1 = fmaxf(mx1, __shfl_xor_sync(0xffffffffu, mx1, 1));
        mx1 = fmaxf(mx1, __shfl_xor_sync(0xffffffffu, mx1, 2));
        float mn0 = fmaxf(m0, mx0), mn1 = fmaxf(m1, mx1);
        float al0 = __expf(m0 - mn0), al1 = __expf(m1 - mn1);
        m0 = mn0; m1 = mn1;

        float sum0 = 0.f, sum1 = 0.f;
#pragma unroll
        for (int nb = 0; nb < 8; nb++) {
            float p00 = __expf(s_[nb][0] - mn0);
            float p01 = __expf(s_[nb][1] - mn0);
            float p10 = __expf(s_[nb][2] - mn1);
            float p11 = __expf(s_[nb][3] - mn1);
            sum0 += p00 + p01;
            sum1 += p10 + p11;
            int col = nb * 8 + 2 * tg;
            *(float2*)&Pw[gq * 68 + col] =
                make_float2(__uint_as_float(f2tf(p00)), __uint_as_float(f2tf(p01)));
            *(float2*)&Pw[(gq + 8) * 68 + col] =
                make_float2(__uint_as_float(f2tf(p10)), __uint_as_float(f2tf(p11)));
        }
        sum0 += __shfl_xor_sync(0xffffffffu, sum0, 1);
        sum0 += __shfl_xor_sync(0xffffffffu, sum0, 2);
        sum1 += __shfl_xor_sync(0xffffffffu, sum1, 1);
        sum1 += __shfl_xor_sync(0xffffffffu, sum1, 2);
        l0 = l0 * al0 + sum0;
        l1 = l1 * al1 + sum1;

#pragma unroll
        for (int nb = 0; nb < 8; nb++) {
            o[nb][0] *= al0; o[nb][1] *= al0;
            o[nb][2] *= al1; o[nb][3] *= al1;
        }
        __syncwarp();   // P store -> P load, warp-private

        // O += P V : A from Pw, B from Vs[d][s]
#pragma unroll
        for (int kk = 0; kk < 8; kk++) {
            uint32_t pa[4];
            pa[0] = __float_as_uint(Pw[(gq)     * 68 + kk * 8 + tg]);
            pa[1] = __float_as_uint(Pw[(gq + 8) * 68 + kk * 8 + tg]);
            pa[2] = __float_as_uint(Pw[(gq)     * 68 + kk * 8 + tg + 4]);
            pa[3] = __float_as_uint(Pw[(gq + 8) * 68 + kk * 8 + tg + 4]);
#pragma unroll
            for (int nb = 0; nb < 8; nb++) {
                const float* vp = &Vs[(nb * 8 + gq) * 68 + kk * 8 + tg];
                uint32_t b0 = __float_as_uint(vp[0]);
                uint32_t b1 = __float_as_uint(vp[4]);
                mma_tf32(o[nb], pa, b0, b1);
            }
        }
        __syncthreads();   // protect Ks/Vs before next staging
    }

    float inv0 = 1.f / l0, inv1 = 1.f / l1;
    float* ab = g_att + ((size_t)b * CCH + hh * 64) * T_LEN;
#pragma unroll
    for (int nb = 0; nb < 8; nb++) {
        int d = nb * 8 + 2 * tg;
        ab[(size_t)(d)     * T_LEN + qrow0]     = o[nb][0] * inv0;
        ab[(size_t)(d + 1) * T_LEN + qrow0]     = o[nb][1] * inv0;
        ab[(size_t)(d)     * T_LEN + qrow0 + 8] = o[nb][2] * inv1;
        ab[(size_t)(d + 1) * T_LEN + qrow0 + 8] = o[nb][3] * inv1;
    }
}

// ---------------- launch --------------------------------------------------
extern "C" void kernel_launch(void* const* d_in, const int* in_sizes, int n_in,
                              void* d_out, int out_size) {
    const float* x      = (const float*)d_in[0];
    const float* norm_w = (const float*)d_in[1];
    const float* norm_b = (const float*)d_in[2];
    const float* qkv_w  = (const float*)d_in[3];
    const float* proj_w = (const float*)d_in[4];
    const float* proj_b = (const float*)d_in[5];
    float* out = (float*)d_out;

    // 1) GroupNorm
    gn_kernel<<<64, 256>>>(x, norm_w, norm_b);

    // 2) QKV projection (tf32 mma): [768,256] @ [256,4096] per batch
    gemm_mma_kernel<0><<<dim3(64, 6, 2), 256>>>(qkv_w, nullptr, nullptr, nullptr);

    // 3) flash attention (tf32 mma): 64 q-tiles x 8 batch-heads, 3 CTAs/SM
    static const int FLASH_SMEM = 3 * 64 * 68 * 4;  // 52224 B
    cudaFuncSetAttribute(flash_mma_kernel, cudaFuncAttributeMaxDynamicSharedMemorySize, FLASH_SMEM);
    flash_mma_kernel<<<dim3(64, 8), 128, FLASH_SMEM>>>();

    // 4) output projection + bias + residual (tf32 mma)
    gemm_mma_kernel<1><<<dim3(64, 2, 2), 256>>>(proj_w, out, proj_b, x);
}

// round 13
// speedup vs baseline: 1.4751x; 1.4751x over previous
#include <cuda_runtime.h>
#include <cstdint>

#define T_LEN 4096
#define CCH   256
#define BATCH 2

// ---------------- scratch (device globals; no allocation allowed) ----------
__device__ float g_xn [BATCH * CCH * T_LEN];          // normalized input [B,C,T]
__device__ float g_qkv[BATCH * 3 * CCH * T_LEN];      // qkv [B,3C,T]
__device__ float g_att[BATCH * CCH * T_LEN];          // attention out [B,C,T]

// ---------------- tf32 helpers --------------------------------------------
__device__ __forceinline__ uint32_t f2tf(float x) {
    uint32_t u;
    asm("cvt.rna.tf32.f32 %0, %1;" : "=r"(u) : "f"(x));
    return u;
}

__device__ __forceinline__ void mma_tf32(float* d, const uint32_t* a,
                                         uint32_t b0, uint32_t b1) {
    asm volatile(
        "mma.sync.aligned.m16n8k8.row.col.f32.tf32.tf32.f32 "
        "{%0,%1,%2,%3}, {%4,%5,%6,%7}, {%8,%9}, {%0,%1,%2,%3};"
        : "+f"(d[0]), "+f"(d[1]), "+f"(d[2]), "+f"(d[3])
        : "r"(a[0]), "r"(a[1]), "r"(a[2]), "r"(a[3]), "r"(b0), "r"(b1));
}

// ---------------- GroupNorm (32 groups of 8 channels, over C/G x T) --------
__global__ void gn_kernel(const float* __restrict__ x,
                          const float* __restrict__ w,
                          const float* __restrict__ bb) {
    int b = blockIdx.x >> 5, g = blockIdx.x & 31;
    const float* xp = x    + ((size_t)b * CCH + g * 8) * T_LEN;
    float*       op = g_xn + ((size_t)b * CCH + g * 8) * T_LEN;
    int tid = threadIdx.x;

    float s = 0.f, s2 = 0.f;
    for (int i = tid; i < 8 * T_LEN; i += 256) {
        float v = xp[i]; s += v; s2 += v * v;
    }
    __shared__ float rs[256], rq[256];
    rs[tid] = s; rq[tid] = s2; __syncthreads();
    for (int off = 128; off; off >>= 1) {
        if (tid < off) { rs[tid] += rs[tid + off]; rq[tid] += rq[tid + off]; }
        __syncthreads();
    }
    __shared__ float sm_mean, sm_rstd;
    if (tid == 0) {
        float mean = rs[0] * (1.f / (8.f * T_LEN));
        float var  = rq[0] * (1.f / (8.f * T_LEN)) - mean * mean;
        sm_mean = mean;
        sm_rstd = rsqrtf(var + 1e-5f);
    }
    __syncthreads();
    float mean = sm_mean, rstd = sm_rstd;
    for (int i = tid; i < 8 * T_LEN; i += 256) {
        int c = g * 8 + (i >> 12);
        op[i] = (xp[i] - mean) * rstd * w[c] + bb[c];
    }
}

// ---------------- GEMM on tensor cores (tf32), shared template -------------
// MODE 0 (QKV): C[768,4096] = qkv_w @ g_xn              (no epilogue)
// MODE 1 (proj): C[256,4096] = proj_w @ g_att + bias + resid
// Block: 256 thr = 8 warps; tile 128m x 64n; k staged 16 wide.
template <int MODE>
__global__ void gemm_mma_kernel(const float* __restrict__ Aw,
                                float* __restrict__ outg,
                                const float* __restrict__ bias,
                                const float* __restrict__ residg) {
    int z = blockIdx.z;
    const float* B = (MODE == 0) ? (g_xn  + (size_t)z * CCH * T_LEN)
                                 : (g_att + (size_t)z * CCH * T_LEN);
    float*       C = (MODE == 0) ? (g_qkv + (size_t)z * 3 * CCH * T_LEN)
                                 : (outg  + (size_t)z * CCH * T_LEN);
    int n0 = blockIdx.x * 64, m0 = blockIdx.y * 128;

    __shared__ float As[128 * 20];
    __shared__ float Bs[64 * 20];

    int tid = threadIdx.x, warp = tid >> 5, lane = tid & 31;
    int gq = lane >> 2, tg = lane & 3;

    float o[8][4] = {};

    for (int k0 = 0; k0 < 256; k0 += 16) {
        // stage A: 128x16, each thread one half-row (8 floats)
        {
            int mi = tid >> 1, j = (tid & 1) * 8;
            const float* src = &Aw[(size_t)(m0 + mi) * 256 + k0 + j];
            float4 v0 = *(const float4*)&src[0];
            float4 v1 = *(const float4*)&src[4];
            float* ap = &As[mi * 20 + j];
            ap[0] = __uint_as_float(f2tf(v0.x));
            ap[1] = __uint_as_float(f2tf(v0.y));
            ap[2] = __uint_as_float(f2tf(v0.z));
            ap[3] = __uint_as_float(f2tf(v0.w));
            ap[4] = __uint_as_float(f2tf(v1.x));
            ap[5] = __uint_as_float(f2tf(v1.y));
            ap[6] = __uint_as_float(f2tf(v1.z));
            ap[7] = __uint_as_float(f2tf(v1.w));
        }
        // stage B: 16k x 64n, transposed into Bs[n][k]
#pragma unroll
        for (int r = 0; r < 4; r++) {
            int idx = tid + r * 256;
            int k = idx >> 6, n = idx & 63;
            Bs[n * 20 + k] =
                __uint_as_float(f2tf(B[(size_t)(k0 + k) * T_LEN + n0 + n]));
        }
        __syncthreads();

#pragma unroll
        for (int kk = 0; kk < 2; kk++) {
            uint32_t a[4];
            const float* arow = &As[(warp * 16 + gq) * 20 + kk * 8 + tg];
            a[0] = __float_as_uint(arow[0]);
            a[1] = __float_as_uint(arow[8 * 20]);
            a[2] = __float_as_uint(arow[4]);
            a[3] = __float_as_uint(arow[8 * 20 + 4]);
#pragma unroll
            for (int nb = 0; nb < 8; nb++) {
                const float* bp = &Bs[(nb * 8 + gq) * 20 + kk * 8 + tg];
                mma_tf32(o[nb], a, __float_as_uint(bp[0]), __float_as_uint(bp[4]));
            }
        }
        __syncthreads();
    }

    int m = m0 + warp * 16 + gq;
#pragma unroll
    for (int nb = 0; nb < 8; nb++) {
        int col = n0 + nb * 8 + 2 * tg;
        float2 r0 = make_float2(o[nb][0], o[nb][1]);
        float2 r1 = make_float2(o[nb][2], o[nb][3]);
        if (MODE == 1) {
            const float* resid = residg + (size_t)z * CCH * T_LEN;
            float b0v = bias[m], b1v = bias[m + 8];
            float2 x0 = *(const float2*)&resid[(size_t)m * T_LEN + col];
            float2 x1 = *(const float2*)&resid[(size_t)(m + 8) * T_LEN + col];
            r0.x += b0v + x0.x; r0.y += b0v + x0.y;
            r1.x += b1v + x1.x; r1.y += b1v + x1.y;
        }
        *(float2*)&C[(size_t)m * T_LEN + col]       = r0;
        *(float2*)&C[(size_t)(m + 8) * T_LEN + col] = r1;
    }
}

// ---------------- flash attention: tf32 mma, 128-query CTAs, 2 CTAs/SM -----
// Block: 128 queries (8 warps x 16 rows), KV tile 64, d=64.
// smem: Ks[64][68] ([s][d], tf32), Vs[64][68] ([d][s], tf32), Ps[128][68]
__global__ __launch_bounds__(256, 2) void flash_mma_kernel() {
    extern __shared__ float sm[];
    float* Ks = sm;                   // 64*68
    float* Vs = sm + 64 * 68;         // 64*68
    float* Ps = sm + 2 * 64 * 68;     // 128*68 (per-warp 16-row slices)

    int bh = blockIdx.y;
    int b = bh >> 2, hh = bh & 3;
    int t0 = blockIdx.x * 128;
    const float* qb = g_qkv + ((size_t)b * 768 + hh * 192) * T_LEN;
    const float* kb = qb + (size_t)64  * T_LEN;
    const float* vb = qb + (size_t)128 * T_LEN;

    int tid = threadIdx.x;
    int warp = tid >> 5, lane = tid & 31;
    int gq = lane >> 2, tg = lane & 3;     // groupID, threadInGroup
    int qrow0 = t0 + warp * 16 + gq;       // global q index of A-row "gq"

    // Q fragments (scale 1/8 folded in), tf32-rounded, register-resident
    uint32_t qa[8][4];
#pragma unroll
    for (int kk = 0; kk < 8; kk++) {
        int d0 = kk * 8 + tg;
        qa[kk][0] = f2tf(qb[(size_t)(d0)     * T_LEN + qrow0]     * 0.125f);
        qa[kk][1] = f2tf(qb[(size_t)(d0)     * T_LEN + qrow0 + 8] * 0.125f);
        qa[kk][2] = f2tf(qb[(size_t)(d0 + 4) * T_LEN + qrow0]     * 0.125f);
        qa[kk][3] = f2tf(qb[(size_t)(d0 + 4) * T_LEN + qrow0 + 8] * 0.125f);
    }

    float o[8][4] = {};
    float m0 = -1e30f, m1 = -1e30f, l0 = 0.f, l1 = 0.f;

    float* Pw = Ps + warp * 16 * 68;   // this warp's P slice

    for (int s0 = 0; s0 < T_LEN; s0 += 64) {
        // stage K [s][68] and V [d][68] (tf32-rounded once here)
        for (int idx = tid; idx < 4096; idx += 256) {
            int d = idx >> 6, s = idx & 63;
            float kv = kb[(size_t)d * T_LEN + s0 + s];
            float vv = vb[(size_t)d * T_LEN + s0 + s];
            Ks[s * 68 + d] = __uint_as_float(f2tf(kv));
            Vs[d * 68 + s] = __uint_as_float(f2tf(vv));
        }
        __syncthreads();

        // S = Q K^T : per warp 16x64, acc fragments s_[nb][4]
        float s_[8][4] = {};
#pragma unroll
        for (int kk = 0; kk < 8; kk++) {
#pragma unroll
            for (int nb = 0; nb < 8; nb++) {
                const float* kp = &Ks[(nb * 8 + gq) * 68 + kk * 8 + tg];
                uint32_t b0 = __float_as_uint(kp[0]);
                uint32_t b1 = __float_as_uint(kp[4]);
                mma_tf32(s_[nb], qa[kk], b0, b1);
            }
        }

        // online softmax: half 0 = rows gq (c0,c1), half 1 = rows gq+8 (c2,c3)
        float mx0 = -1e30f, mx1 = -1e30f;
#pragma unroll
        for (int nb = 0; nb < 8; nb++) {
            mx0 = fmaxf(mx0, fmaxf(s_[nb][0], s_[nb][1]));
            mx1 = fmaxf(mx1, fmaxf(s_[nb][2], s_[nb][3]));
        }
        mx0 = fmaxf(mx0, __shfl_xor_sync(0xffffffffu, mx0, 1));
        mx0 = fmaxf(mx0, __shfl_xor_sync(0xffffffffu, mx0, 2));
        mx1 = fmaxf(mx1, __shfl_xor_sync(0xffffffffu, mx1, 1));
        mx1 = fmaxf(mx1, __shfl_xor_sync(0xffffffffu, mx1, 2));
        float mn0 = fmaxf(m0, mx0), mn1 = fmaxf(m1, mx1);
        float al0 = __expf(m0 - mn0), al1 = __expf(m1 - mn1);
        m0 = mn0; m1 = mn1;

        float sum0 = 0.f, sum1 = 0.f;
#pragma unroll
        for (int nb = 0; nb < 8; nb++) {
            float p00 = __expf(s_[nb][0] - mn0);
            float p01 = __expf(s_[nb][1] - mn0);
            float p10 = __expf(s_[nb][2] - mn1);
            float p11 = __expf(s_[nb][3] - mn1);
            sum0 += p00 + p01;
            sum1 += p10 + p11;
            int col = nb * 8 + 2 * tg;
            *(float2*)&Pw[gq * 68 + col] =
                make_float2(__uint_as_float(f2tf(p00)), __uint_as_float(f2tf(p01)));
            *(float2*)&Pw[(gq + 8) * 68 + col] =
                make_float2(__uint_as_float(f2tf(p10)), __uint_as_float(f2tf(p11)));
        }
        sum0 += __shfl_xor_sync(0xffffffffu, sum0, 1);
        sum0 += __shfl_xor_sync(0xffffffffu, sum0, 2);
        sum1 += __shfl_xor_sync(0xffffffffu, sum1, 1);
        sum1 += __shfl_xor_sync(0xffffffffu, sum1, 2);
        l0 = l0 * al0 + sum0;
        l1 = l1 * al1 + sum1;

#pragma unroll
        for (int nb = 0; nb < 8; nb++) {
            o[nb][0] *= al0; o[nb][1] *= al0;
            o[nb][2] *= al1; o[nb][3] *= al1;
        }
        __syncwarp();   // P store -> P load, warp-private

        // O += P V : A from Pw, B from Vs[d][s]
#pragma unroll
        for (int kk = 0; kk < 8; kk++) {
            uint32_t pa[4];
            pa[0] = __float_as_uint(Pw[(gq)     * 68 + kk * 8 + tg]);
            pa[1] = __float_as_uint(Pw[(gq + 8) * 68 + kk * 8 + tg]);
            pa[2] = __float_as_uint(Pw[(gq)     * 68 + kk * 8 + tg + 4]);
            pa[3] = __float_as_uint(Pw[(gq + 8) * 68 + kk * 8 + tg + 4]);
#pragma unroll
            for (int nb = 0; nb < 8; nb++) {
                const float* vp = &Vs[(nb * 8 + gq) * 68 + kk * 8 + tg];
                uint32_t b0 = __float_as_uint(vp[0]);
                uint32_t b1 = __float_as_uint(vp[4]);
                mma_tf32(o[nb], pa, b0, b1);
            }
        }
        __syncthreads();   // protect Ks/Vs before next staging
    }

    float inv0 = 1.f / l0, inv1 = 1.f / l1;
    float* ab = g_att + ((size_t)b * CCH + hh * 64) * T_LEN;
#pragma unroll
    for (int nb = 0; nb < 8; nb++) {
        int d = nb * 8 + 2 * tg;
        ab[(size_t)(d)     * T_LEN + qrow0]     = o[nb][0] * inv0;
        ab[(size_t)(d + 1) * T_LEN + qrow0]     = o[nb][1] * inv0;
        ab[(size_t)(d)     * T_LEN + qrow0 + 8] = o[nb][2] * inv1;
        ab[(size_t)(d + 1) * T_LEN + qrow0 + 8] = o[nb][3] * inv1;
    }
}

// ---------------- launch --------------------------------------------------
extern "C" void kernel_launch(void* const* d_in, const int* in_sizes, int n_in,
                              void* d_out, int out_size) {
    const float* x      = (const float*)d_in[0];
    const float* norm_w = (const float*)d_in[1];
    const float* norm_b = (const float*)d_in[2];
    const float* qkv_w  = (const float*)d_in[3];
    const float* proj_w = (const float*)d_in[4];
    const float* proj_b = (const float*)d_in[5];
    float* out = (float*)d_out;

    // 1) GroupNorm
    gn_kernel<<<64, 256>>>(x, norm_w, norm_b);

    // 2) QKV projection (tf32 mma): [768,256] @ [256,4096] per batch
    gemm_mma_kernel<0><<<dim3(64, 6, 2), 256>>>(qkv_w, nullptr, nullptr, nullptr);

    // 3) flash attention (tf32 mma): 32 q-tiles x 8 batch-heads, 2 CTAs/SM
    static const int FLASH_SMEM = (2 * 64 * 68 + 128 * 68) * 4;  // 69632 B
    cudaFuncSetAttribute(flash_mma_kernel, cudaFuncAttributeMaxDynamicSharedMemorySize, FLASH_SMEM);
    flash_mma_kernel<<<dim3(32, 8), 256, FLASH_SMEM>>>();

    // 4) output projection + bias + residual (tf32 mma)
    gemm_mma_kernel<1><<<dim3(64, 2, 2), 256>>>(proj_w, out, proj_b, x);
}